// round 14
// baseline (speedup 1.0000x reference)
#include <cuda_runtime.h>
#include <cstdint>
#include <cstddef>

#define DMODEL 2048
#define NH 16
#define HD 128
#define B_ 8
#define S_ 16
#define P_ 4096
#define T_ 4112           // P + S
#define M_ 128            // B * S
#define NCH 257           // T_/16
#define NSPLIT_G 6        // grid-z key splits (768 CTAs -> 5+ CTAs/SM)
#define NSPT 12           // total partials per bh = NSPLIT_G * 2 in-CTA key-halves

// ---------------- scratch (static device globals; no allocation) ----------------
__device__ float g_qkv[M_ * 3 * DMODEL];     // QKV GEMM output [128][6144]
__device__ float g_q[B_ * NH * S_ * HD];     // q, pre-scaled, [b][h][s][d]
__device__ float g_attn[M_ * DMODEL];        // attention output [b*16+s][2048]
__device__ float g_pm[M_ * NSPT * S_];       // partial max   [bh][spp][s]
__device__ float g_pl[M_ * NSPT * S_];       // partial l     [bh][spp][s]
__device__ float g_pacc[M_ * NSPT * S_ * HD]; // partial acc  [bh][spp][s][d]

__device__ __forceinline__ unsigned smem_u32(const void* p) {
    return (unsigned)__cvta_generic_to_shared(p);
}
#define CP_ASYNC16(dst, src) asm volatile("cp.async.cg.shared.global [%0], [%1], 16;" :: "r"(dst), "l"(src))
#define CP_COMMIT()          asm volatile("cp.async.commit_group;")
#define CP_WAIT0()           asm volatile("cp.async.wait_group 0;")

// ---------------- init: seed bias into GEMM accumulators ----------------
__global__ void k_init(const float* __restrict__ bp, const float* __restrict__ bf,
                       float* __restrict__ out_ff) {
    int i = blockIdx.x * 256 + threadIdx.x;           // grid covers 786432
    g_qkv[i] = bp[i % (3 * DMODEL)];
    if (i < M_ * DMODEL) out_ff[i] = bf[i & (DMODEL - 1)];
}

// ---------------- fp32 GEMM: C[128][N] += A[128][2048] * W[2048][N] ----------------
__global__ __launch_bounds__(256) void k_gemm(const float* __restrict__ Ain,
                                              const float* __restrict__ W,
                                              float* __restrict__ Cout,
                                              int N, int use_globals) {
    __shared__ float As[32][129];
    __shared__ float Bs[32][132];
    const float* A = use_globals ? (const float*)g_attn : Ain;
    float* C       = use_globals ? Cout : (float*)g_qkv;

    const int n0 = blockIdx.x * 128;
    const int c0 = (blockIdx.y * 64) / gridDim.y;
    const int c1 = ((blockIdx.y + 1) * 64) / gridDim.y;
    const int t = threadIdx.x;
    const int ty = t >> 4, tx = t & 15;

    float acc[8][8];
#pragma unroll
    for (int i = 0; i < 8; i++)
#pragma unroll
        for (int j = 0; j < 8; j++) acc[i][j] = 0.f;

    for (int c = c0; c < c1; ++c) {
        const int k0 = c * 32;
#pragma unroll
        for (int i = 0; i < 4; ++i) {
            int j = t + i * 256;
            int m = j >> 3, kq = j & 7;
            float4 va = *(const float4*)(A + (size_t)m * DMODEL + k0 + kq * 4);
            As[kq * 4 + 0][m] = va.x; As[kq * 4 + 1][m] = va.y;
            As[kq * 4 + 2][m] = va.z; As[kq * 4 + 3][m] = va.w;
        }
#pragma unroll
        for (int i = 0; i < 4; ++i) {
            int j = t + i * 256;
            int kr = j >> 5, nc = j & 31;
            *(float4*)&Bs[kr][nc * 4] = *(const float4*)(W + (size_t)(k0 + kr) * N + n0 + nc * 4);
        }
        __syncthreads();
#pragma unroll
        for (int k = 0; k < 32; ++k) {
            float a[8], b[8];
#pragma unroll
            for (int i = 0; i < 8; i++) a[i] = As[k][ty * 8 + i];
            *(float4*)&b[0] = *(const float4*)&Bs[k][tx * 4];
            *(float4*)&b[4] = *(const float4*)&Bs[k][64 + tx * 4];
#pragma unroll
            for (int i = 0; i < 8; i++)
#pragma unroll
                for (int j = 0; j < 8; j++) acc[i][j] += a[i] * b[j];
        }
        __syncthreads();
    }
#pragma unroll
    for (int i = 0; i < 8; i++) {
        int m = ty * 8 + i;
#pragma unroll
        for (int j = 0; j < 4; j++)
            atomicAdd(&C[(size_t)m * N + n0 + tx * 4 + j], acc[i][j]);
#pragma unroll
        for (int j = 0; j < 4; j++)
            atomicAdd(&C[(size_t)m * N + n0 + 64 + tx * 4 + j], acc[i][4 + j]);
    }
}

// ---------------- scatter QKV: q -> g_q (pre-scaled), k/v -> out_kv rows P..P+15 ----------------
__global__ void k_scatter(float* __restrict__ out_kv) {
    int i = blockIdx.x * 256 + threadIdx.x;               // covers 786432
    int m = i / (3 * DMODEL), col = i % (3 * DMODEL);
    int b = m >> 4, s = m & 15;
    int which = col >> 11;                                // 0=q 1=k 2=v
    int hc = col & 2047;
    int h = hc >> 7, d = hc & 127;
    float v = g_qkv[i];
    if (which == 0) {
        g_q[(((size_t)(b * NH + h) * S_ + s) << 7) + d] = v * 0.08838834764831845f; // 1/sqrt(128)
    } else {
        size_t off = ((((size_t)(which - 1) * B_ + b) * NH + h) * T_ + (P_ + s)) * HD + d;
        out_kv[off] = v;
    }
}

// ---------------- fused attention + KV copy: warp-autonomous 8q x 8k streams ----------------
// CTA = 128 threads = 4 warps = (q-half qh, key-half kh). Each warp is an
// independent online-softmax stream. K/Q/V half-tiles each read from smem
// exactly once per warp; p/f via warp-private smem (__syncwarp only).
// ONE CTA barrier per chunk. launch_bounds(128,5) pins 5 CTAs/SM residency.
__global__ __launch_bounds__(128, 5) void k_attn(const float* __restrict__ pk,
                                                 const float* __restrict__ pv,
                                                 const int* __restrict__ mask,
                                                 float* __restrict__ out_kv) {
    __shared__ float qs[S_][132];
    __shared__ float kb[2][16][132];
    __shared__ float vb[2][16][132];
    __shared__ __align__(16) float p_s[4][8][8];   // [warp][key j][q row]
    __shared__ float f_s[4][8];                    // [warp][q row]

    const int h = blockIdx.x, b = blockIdx.y, sp = blockIdx.z;
    const int bh = b * NH + h;
    const int t = threadIdx.x;
    const int w = t >> 5, lane = t & 31;
    const int qh = w >> 1, kh = w & 1;
    const int kj = lane & 7, qp = lane >> 3;       // qp in 0..3
    const int row0 = qh * 8 + qp * 2, row1 = row0 + 1;

    {   // load q tile (pre-scaled): 512 float4 / 128 threads
        const float* qsrc = g_q + (size_t)bh * S_ * HD;
#pragma unroll
        for (int i = 0; i < 4; ++i) {
            int j = t + i * 128;
            int row = j >> 5, seg = j & 31;
            *(float4*)&qs[row][seg * 4] = ((const float4*)qsrc)[j];
        }
    }

    float m0 = -1e30f, m1 = -1e30f, l0 = 0.f, l1 = 0.f;
    float acc[8][4];
#pragma unroll
    for (int q = 0; q < 8; ++q)
#pragma unroll
        for (int i = 0; i < 4; ++i) acc[q][i] = 0.f;

    const size_t kvbase = (size_t)bh * (size_t)P_ * HD;
    const int ch0 = (sp * NCH) / NSPLIT_G;
    const int ch1 = ((sp + 1) * NCH) / NSPLIT_G;

    auto issue = [&](int c, int bufi) {
#pragma unroll
        for (int i = 0; i < 8; ++i) {
            int j = t + i * 128;                  // 1024 float4 = 16 K + 16 V rows
            int r = j >> 5, seg = j & 31;
            int row = r & 15;
            bool isv = r >= 16;
            int key = c * 16 + row;
            const float* src;
            if (key < P_) src = (isv ? pv : pk) + kvbase + (size_t)key * HD + seg * 4;
            else          src = out_kv + ((((size_t)(isv ? 1 : 0) * B_ + b) * NH + h) * T_ + key) * HD + seg * 4;
            float* dstp = &(isv ? vb : kb)[bufi][row][seg * 4];
            CP_ASYNC16(smem_u32(dstp), src);
        }
    };

    issue(ch0, ch0 & 1);                          // parity-correct prologue (ch0 may be odd)
    CP_COMMIT();

    const int* mrow0 = mask + (size_t)(b * S_ + row0) * T_;
    const int* mrow1 = mask + (size_t)(b * S_ + row1) * T_;

    for (int c = ch0; c < ch1; ++c) {
        const int cur = c & 1;
        CP_WAIT0();
        __syncthreads();                         // chunk c visible; other buf free
        if (c + 1 < ch1) issue(c + 1, cur ^ 1);
        CP_COMMIT();

        // ---- scores: lane -> key (kh*8+kj), rows row0,row1; dual accumulators ----
        const float* krow = &kb[cur][kh * 8 + kj][0];
        float a0 = 0.f, b0 = 0.f, a1 = 0.f, b1 = 0.f;
#pragma unroll
        for (int d4 = 0; d4 < 32; d4 += 2) {
            float4 k0 = *(const float4*)&krow[d4 * 4];
            float4 k1 = *(const float4*)&krow[d4 * 4 + 4];
            float4 q00 = *(const float4*)&qs[row0][d4 * 4];
            float4 q01 = *(const float4*)&qs[row0][d4 * 4 + 4];
            float4 q10 = *(const float4*)&qs[row1][d4 * 4];
            float4 q11 = *(const float4*)&qs[row1][d4 * 4 + 4];
            a0 += k0.x * q00.x + k0.y * q00.y + k0.z * q00.z + k0.w * q00.w;
            b0 += k1.x * q01.x + k1.y * q01.y + k1.z * q01.z + k1.w * q01.w;
            a1 += k0.x * q10.x + k0.y * q10.y + k0.z * q10.z + k0.w * q10.w;
            b1 += k1.x * q11.x + k1.y * q11.y + k1.z * q11.z + k1.w * q11.w;
        }
        float s0 = a0 + b0, s1 = a1 + b1;
        int keyg = c * 16 + kh * 8 + kj;
        if (mrow0[keyg] == 0) s0 = -65504.f;
        if (mrow1[keyg] == 0) s1 = -65504.f;

        // ---- warp-local softmax: 8-lane butterflies over kj ----
        float cm0 = s0, cm1 = s1;
#pragma unroll
        for (int o = 4; o > 0; o >>= 1) {
            cm0 = fmaxf(cm0, __shfl_xor_sync(0xffffffffu, cm0, o));
            cm1 = fmaxf(cm1, __shfl_xor_sync(0xffffffffu, cm1, o));
        }
        float nm0 = fmaxf(m0, cm0), nm1 = fmaxf(m1, cm1);
        float f0 = __expf(m0 - nm0), f1 = __expf(m1 - nm1);
        float p0 = __expf(s0 - nm0), p1 = __expf(s1 - nm1);
        m0 = nm0; m1 = nm1;
        float su0 = p0, su1 = p1;
#pragma unroll
        for (int o = 4; o > 0; o >>= 1) {
            su0 += __shfl_xor_sync(0xffffffffu, su0, o);
            su1 += __shfl_xor_sync(0xffffffffu, su1, o);
        }
        l0 = l0 * f0 + su0;
        l1 = l1 * f1 + su1;

        p_s[w][kj][qp * 2]     = p0;              // warp-private region
        p_s[w][kj][qp * 2 + 1] = p1;
        if (kj == 0) { f_s[w][qp * 2] = f0; f_s[w][qp * 2 + 1] = f1; }
        __syncwarp();

        // ---- PV: lane = d-segment (lane*4), all 8 rows of this warp's half ----
#pragma unroll
        for (int q = 0; q < 8; ++q) {
            float fq = f_s[w][q];
            acc[q][0] *= fq; acc[q][1] *= fq; acc[q][2] *= fq; acc[q][3] *= fq;
        }
#pragma unroll
        for (int j = 0; j < 8; ++j) {
            float4 vv = *(const float4*)&vb[cur][kh * 8 + j][lane * 4];
            float4 pa = *(const float4*)&p_s[w][j][0];
            float4 pb = *(const float4*)&p_s[w][j][4];
            float pj[8] = {pa.x, pa.y, pa.z, pa.w, pb.x, pb.y, pb.z, pb.w};
#pragma unroll
            for (int q = 0; q < 8; ++q) {
                acc[q][0] += pj[q] * vv.x; acc[q][1] += pj[q] * vv.y;
                acc[q][2] += pj[q] * vv.z; acc[q][3] += pj[q] * vv.w;
            }
        }

        // ---- prefix copy-out from smem (new rows already in out_kv) ----
#pragma unroll
        for (int i = 0; i < 8; ++i) {
            int j = t + i * 128;
            int r = j >> 5, seg = j & 31;
            int row = r & 15;
            bool isv = r >= 16;
            int ckey = c * 16 + row;
            if (ckey < P_) {
                float4 val = *(const float4*)&(isv ? vb : kb)[cur][row][seg * 4];
                __stcs((float4*)(out_kv + ((((size_t)(isv ? 1 : 0) * B_ + b) * NH + h) * T_ + ckey) * HD + seg * 4), val);
            }
        }
    }

    // ---- write partials: stream id spp = sp*2 + kh ----
    const int spp = sp * 2 + kh;
    if (kj == 0) {
        size_t base = ((size_t)bh * NSPT + spp) * S_;
        g_pm[base + row0] = m0; g_pm[base + row1] = m1;
        g_pl[base + row0] = l0; g_pl[base + row1] = l1;
    }
    float* pa = g_pacc + (((size_t)bh * NSPT + spp) * S_ + qh * 8) * HD;
#pragma unroll
    for (int q = 0; q < 8; ++q) {
        float4 v = make_float4(acc[q][0], acc[q][1], acc[q][2], acc[q][3]);
        *(float4*)&pa[(size_t)q * HD + lane * 4] = v;
    }
}

// ---------------- combine split partials -> g_attn ----------------
__global__ __launch_bounds__(256) void k_comb() {
    const int bh = blockIdx.x;
    const int t = threadIdx.x;
    const int s = t >> 4, lj = t & 15;
    const int b = bh >> 4, h = bh & 15;

    float mv[NSPT], lv[NSPT];
#pragma unroll
    for (int sp = 0; sp < NSPT; ++sp) {
        size_t pidx = ((size_t)bh * NSPT + sp) * S_ + s;
        mv[sp] = g_pm[pidx];
        lv[sp] = g_pl[pidx];
    }
    float M = mv[0];
#pragma unroll
    for (int sp = 1; sp < NSPT; ++sp) M = fmaxf(M, mv[sp]);
    float w[NSPT], L = 0.f;
#pragma unroll
    for (int sp = 0; sp < NSPT; ++sp) { w[sp] = __expf(mv[sp] - M); L += lv[sp] * w[sp]; }
    float linv = 1.f / L;

    float o[8];
#pragma unroll
    for (int i = 0; i < 8; i++) o[i] = 0.f;
#pragma unroll
    for (int sp = 0; sp < NSPT; ++sp) {
        const float* pa = g_pacc + (((size_t)bh * NSPT + sp) * S_ + s) * HD;
        float4 a0 = *(const float4*)&pa[lj * 4];
        float4 a1 = *(const float4*)&pa[64 + lj * 4];
        o[0] += w[sp] * a0.x; o[1] += w[sp] * a0.y; o[2] += w[sp] * a0.z; o[3] += w[sp] * a0.w;
        o[4] += w[sp] * a1.x; o[5] += w[sp] * a1.y; o[6] += w[sp] * a1.z; o[7] += w[sp] * a1.w;
    }
    float* dst = g_attn + (size_t)(b * S_ + s) * DMODEL + h * HD;
#pragma unroll
    for (int i = 0; i < 4; i++) dst[lj * 4 + i]      = o[i]     * linv;
#pragma unroll
    for (int i = 0; i < 4; i++) dst[64 + lj * 4 + i] = o[4 + i] * linv;
}

// ---------------- launch ----------------
extern "C" void kernel_launch(void* const* d_in, const int* in_sizes, int n_in,
                              void* d_out, int out_size) {
    const float* x    = (const float*)d_in[0];
    const float* pk   = (const float*)d_in[1];
    const float* pv   = (const float*)d_in[2];
    const int*   mask = (const int*)  d_in[3];
    const float* Wp   = (const float*)d_in[4];
    const float* bp   = (const float*)d_in[5];
    const float* Wf   = (const float*)d_in[6];
    const float* bf   = (const float*)d_in[7];
    float* out    = (float*)d_out;
    float* out_ff = out;                               // ff_o: 128*2048 floats
    float* out_kv = out + (size_t)M_ * DMODEL;         // next_prefix_kv: [2][8][16][4112][128]

    k_init   <<<3072, 256>>>(bp, bf, out_ff);
    k_gemm   <<<dim3(48, 3), 256>>>(x, Wp, nullptr, 3 * DMODEL, 0);   // QKV, 144 blocks
    k_scatter<<<3072, 256>>>(out_kv);
    k_attn   <<<dim3(NH, B_, NSPLIT_G), 128>>>(pk, pv, mask, out_kv); // 768 blocks x 4 warps
    k_comb   <<<M_, 256>>>();
    k_gemm   <<<dim3(16, 8), 256>>>(nullptr, Wf, out_ff, DMODEL, 1);  // FF, 128 blocks
}

// round 17
// speedup vs baseline: 1.0811x; 1.0811x over previous
#include <cuda_runtime.h>
#include <cstdint>
#include <cstddef>

#define DMODEL 2048
#define NH 16
#define HD 128
#define B_ 8
#define S_ 16
#define P_ 4096
#define T_ 4112           // P + S
#define M_ 128            // B * S
#define NCH 257           // T_/16
#define NSPLIT_G 5        // grid-z key splits: 640 CTAs = ONE wave at 5 CTAs/SM
#define NSPT 10           // total partials per bh = NSPLIT_G * 2 in-CTA key-halves

// ---------------- scratch (static device globals; no allocation) ----------------
__device__ float g_qkv[M_ * 3 * DMODEL];     // QKV GEMM output [128][6144]
__device__ float g_q[B_ * NH * S_ * HD];     // q, pre-scaled, [b][h][s][d]
__device__ float g_attn[M_ * DMODEL];        // attention output [b*16+s][2048]
__device__ float g_pm[M_ * NSPT * S_];       // partial max   [bh][spp][s]
__device__ float g_pl[M_ * NSPT * S_];       // partial l     [bh][spp][s]
__device__ float g_pacc[M_ * NSPT * S_ * HD]; // partial acc  [bh][spp][s][d]

__device__ __forceinline__ unsigned smem_u32(const void* p) {
    return (unsigned)__cvta_generic_to_shared(p);
}
#define CP_ASYNC16(dst, src) asm volatile("cp.async.cg.shared.global [%0], [%1], 16;" :: "r"(dst), "l"(src))
#define CP_COMMIT()          asm volatile("cp.async.commit_group;")
#define CP_WAIT0()           asm volatile("cp.async.wait_group 0;")

// ---------------- init: seed bias into GEMM accumulators ----------------
__global__ void k_init(const float* __restrict__ bp, const float* __restrict__ bf,
                       float* __restrict__ out_ff) {
    int i = blockIdx.x * 256 + threadIdx.x;           // grid covers 786432
    g_qkv[i] = bp[i % (3 * DMODEL)];
    if (i < M_ * DMODEL) out_ff[i] = bf[i & (DMODEL - 1)];
}

// ---------------- fp32 GEMM: C[128][N] += A[128][2048] * W[2048][N] ----------------
__global__ __launch_bounds__(256) void k_gemm(const float* __restrict__ Ain,
                                              const float* __restrict__ W,
                                              float* __restrict__ Cout,
                                              int N, int use_globals) {
    __shared__ float As[32][129];
    __shared__ float Bs[32][132];
    const float* A = use_globals ? (const float*)g_attn : Ain;
    float* C       = use_globals ? Cout : (float*)g_qkv;

    const int n0 = blockIdx.x * 128;
    const int c0 = (blockIdx.y * 64) / gridDim.y;
    const int c1 = ((blockIdx.y + 1) * 64) / gridDim.y;
    const int t = threadIdx.x;
    const int ty = t >> 4, tx = t & 15;

    float acc[8][8];
#pragma unroll
    for (int i = 0; i < 8; i++)
#pragma unroll
        for (int j = 0; j < 8; j++) acc[i][j] = 0.f;

    for (int c = c0; c < c1; ++c) {
        const int k0 = c * 32;
#pragma unroll
        for (int i = 0; i < 4; ++i) {
            int j = t + i * 256;
            int m = j >> 3, kq = j & 7;
            float4 va = *(const float4*)(A + (size_t)m * DMODEL + k0 + kq * 4);
            As[kq * 4 + 0][m] = va.x; As[kq * 4 + 1][m] = va.y;
            As[kq * 4 + 2][m] = va.z; As[kq * 4 + 3][m] = va.w;
        }
#pragma unroll
        for (int i = 0; i < 4; ++i) {
            int j = t + i * 256;
            int kr = j >> 5, nc = j & 31;
            *(float4*)&Bs[kr][nc * 4] = *(const float4*)(W + (size_t)(k0 + kr) * N + n0 + nc * 4);
        }
        __syncthreads();
#pragma unroll
        for (int k = 0; k < 32; ++k) {
            float a[8], b[8];
#pragma unroll
            for (int i = 0; i < 8; i++) a[i] = As[k][ty * 8 + i];
            *(float4*)&b[0] = *(const float4*)&Bs[k][tx * 4];
            *(float4*)&b[4] = *(const float4*)&Bs[k][64 + tx * 4];
#pragma unroll
            for (int i = 0; i < 8; i++)
#pragma unroll
                for (int j = 0; j < 8; j++) acc[i][j] += a[i] * b[j];
        }
        __syncthreads();
    }
#pragma unroll
    for (int i = 0; i < 8; i++) {
        int m = ty * 8 + i;
#pragma unroll
        for (int j = 0; j < 4; j++)
            atomicAdd(&C[(size_t)m * N + n0 + tx * 4 + j], acc[i][j]);
#pragma unroll
        for (int j = 0; j < 4; j++)
            atomicAdd(&C[(size_t)m * N + n0 + 64 + tx * 4 + j], acc[i][4 + j]);
    }
}

// ---------------- scatter QKV: q -> g_q (pre-scaled), k/v -> out_kv rows P..P+15 ----------------
__global__ void k_scatter(float* __restrict__ out_kv) {
    int i = blockIdx.x * 256 + threadIdx.x;               // covers 786432
    int m = i / (3 * DMODEL), col = i % (3 * DMODEL);
    int b = m >> 4, s = m & 15;
    int which = col >> 11;                                // 0=q 1=k 2=v
    int hc = col & 2047;
    int h = hc >> 7, d = hc & 127;
    float v = g_qkv[i];
    if (which == 0) {
        g_q[(((size_t)(b * NH + h) * S_ + s) << 7) + d] = v * 0.08838834764831845f; // 1/sqrt(128)
    } else {
        size_t off = ((((size_t)(which - 1) * B_ + b) * NH + h) * T_ + (P_ + s)) * HD + d;
        out_kv[off] = v;
    }
}

// ---------------- fused attention + KV copy: warp-autonomous 8q x 8k streams ----------------
// CTA = 128 threads = 4 warps = (q-half qh, key-half kh). Each warp is an
// independent online-softmax stream. K/Q/V half-tiles each read from smem
// exactly once per warp; p/f via warp-private smem (__syncwarp only).
// ONE CTA barrier per chunk. launch_bounds(128,5); grid 640 = single wave.
__global__ __launch_bounds__(128, 5) void k_attn(const float* __restrict__ pk,
                                                 const float* __restrict__ pv,
                                                 const int* __restrict__ mask,
                                                 float* __restrict__ out_kv) {
    __shared__ float qs[S_][132];
    __shared__ float kb[2][16][132];     // padded: kj-lanes read row-strided
    __shared__ float vb[2][16][128];     // unpadded: PV reads lane-contiguous
    __shared__ __align__(16) float p_s[4][8][8];   // [warp][key j][q row]
    __shared__ float f_s[4][8];                    // [warp][q row]

    const int h = blockIdx.x, b = blockIdx.y, sp = blockIdx.z;
    const int bh = b * NH + h;
    const int t = threadIdx.x;
    const int w = t >> 5, lane = t & 31;
    const int qh = w >> 1, kh = w & 1;
    const int kj = lane & 7, qp = lane >> 3;       // qp in 0..3
    const int row0 = qh * 8 + qp * 2, row1 = row0 + 1;

    {   // load q tile (pre-scaled): 512 float4 / 128 threads
        const float* qsrc = g_q + (size_t)bh * S_ * HD;
#pragma unroll
        for (int i = 0; i < 4; ++i) {
            int j = t + i * 128;
            int row = j >> 5, seg = j & 31;
            *(float4*)&qs[row][seg * 4] = ((const float4*)qsrc)[j];
        }
    }

    float m0 = -1e30f, m1 = -1e30f, l0 = 0.f, l1 = 0.f;
    float acc[8][4];
#pragma unroll
    for (int q = 0; q < 8; ++q)
#pragma unroll
        for (int i = 0; i < 4; ++i) acc[q][i] = 0.f;

    const size_t kvbase = (size_t)bh * (size_t)P_ * HD;
    const int ch0 = (sp * NCH) / NSPLIT_G;
    const int ch1 = ((sp + 1) * NCH) / NSPLIT_G;

    auto issue = [&](int c, int bufi) {
#pragma unroll
        for (int i = 0; i < 8; ++i) {
            int j = t + i * 128;                  // 1024 float4 = 16 K + 16 V rows
            int r = j >> 5, seg = j & 31;
            int row = r & 15;
            bool isv = r >= 16;
            int key = c * 16 + row;
            const float* src;
            if (key < P_) src = (isv ? pv : pk) + kvbase + (size_t)key * HD + seg * 4;
            else          src = out_kv + ((((size_t)(isv ? 1 : 0) * B_ + b) * NH + h) * T_ + key) * HD + seg * 4;
            float* dstp = isv ? &vb[bufi][row][seg * 4] : &kb[bufi][row][seg * 4];
            CP_ASYNC16(smem_u32(dstp), src);
        }
    };

    issue(ch0, ch0 & 1);                          // parity-correct prologue (ch0 may be odd)
    CP_COMMIT();

    const int* mrow0 = mask + (size_t)(b * S_ + row0) * T_;
    const int* mrow1 = mask + (size_t)(b * S_ + row1) * T_;

    for (int c = ch0; c < ch1; ++c) {
        const int cur = c & 1;
        CP_WAIT0();
        __syncthreads();                         // chunk c visible; other buf free
        if (c + 1 < ch1) issue(c + 1, cur ^ 1);
        CP_COMMIT();

        // ---- scores: lane -> key (kh*8+kj), rows row0,row1; dual accumulators ----
        const float* krow = &kb[cur][kh * 8 + kj][0];
        float a0 = 0.f, b0 = 0.f, a1 = 0.f, b1 = 0.f;
#pragma unroll
        for (int d4 = 0; d4 < 32; d4 += 2) {
            float4 k0 = *(const float4*)&krow[d4 * 4];
            float4 k1 = *(const float4*)&krow[d4 * 4 + 4];
            float4 q00 = *(const float4*)&qs[row0][d4 * 4];
            float4 q01 = *(const float4*)&qs[row0][d4 * 4 + 4];
            float4 q10 = *(const float4*)&qs[row1][d4 * 4];
            float4 q11 = *(const float4*)&qs[row1][d4 * 4 + 4];
            a0 += k0.x * q00.x + k0.y * q00.y + k0.z * q00.z + k0.w * q00.w;
            b0 += k1.x * q01.x + k1.y * q01.y + k1.z * q01.z + k1.w * q01.w;
            a1 += k0.x * q10.x + k0.y * q10.y + k0.z * q10.z + k0.w * q10.w;
            b1 += k1.x * q11.x + k1.y * q11.y + k1.z * q11.z + k1.w * q11.w;
        }
        float s0 = a0 + b0, s1 = a1 + b1;
        int keyg = c * 16 + kh * 8 + kj;
        if (mrow0[keyg] == 0) s0 = -65504.f;
        if (mrow1[keyg] == 0) s1 = -65504.f;

        // ---- warp-local softmax: 8-lane butterflies over kj ----
        float cm0 = s0, cm1 = s1;
#pragma unroll
        for (int o = 4; o > 0; o >>= 1) {
            cm0 = fmaxf(cm0, __shfl_xor_sync(0xffffffffu, cm0, o));
            cm1 = fmaxf(cm1, __shfl_xor_sync(0xffffffffu, cm1, o));
        }
        float nm0 = fmaxf(m0, cm0), nm1 = fmaxf(m1, cm1);
        float f0 = __expf(m0 - nm0), f1 = __expf(m1 - nm1);
        float p0 = __expf(s0 - nm0), p1 = __expf(s1 - nm1);
        m0 = nm0; m1 = nm1;
        float su0 = p0, su1 = p1;
#pragma unroll
        for (int o = 4; o > 0; o >>= 1) {
            su0 += __shfl_xor_sync(0xffffffffu, su0, o);
            su1 += __shfl_xor_sync(0xffffffffu, su1, o);
        }
        l0 = l0 * f0 + su0;
        l1 = l1 * f1 + su1;

        p_s[w][kj][qp * 2]     = p0;              // warp-private region
        p_s[w][kj][qp * 2 + 1] = p1;
        if (kj == 0) { f_s[w][qp * 2] = f0; f_s[w][qp * 2 + 1] = f1; }
        __syncwarp();

        // ---- PV: lane = d-segment (lane*4), all 8 rows of this warp's half ----
#pragma unroll
        for (int q = 0; q < 8; ++q) {
            float fq = f_s[w][q];
            acc[q][0] *= fq; acc[q][1] *= fq; acc[q][2] *= fq; acc[q][3] *= fq;
        }
#pragma unroll
        for (int j = 0; j < 8; ++j) {
            float4 vv = *(const float4*)&vb[cur][kh * 8 + j][lane * 4];
            float4 pa = *(const float4*)&p_s[w][j][0];
            float4 pb = *(const float4*)&p_s[w][j][4];
            float pj[8] = {pa.x, pa.y, pa.z, pa.w, pb.x, pb.y, pb.z, pb.w};
#pragma unroll
            for (int q = 0; q < 8; ++q) {
                acc[q][0] += pj[q] * vv.x; acc[q][1] += pj[q] * vv.y;
                acc[q][2] += pj[q] * vv.z; acc[q][3] += pj[q] * vv.w;
            }
        }

        // ---- prefix copy-out from smem (new rows already in out_kv) ----
#pragma unroll
        for (int i = 0; i < 8; ++i) {
            int j = t + i * 128;
            int r = j >> 5, seg = j & 31;
            int row = r & 15;
            bool isv = r >= 16;
            int ckey = c * 16 + row;
            if (ckey < P_) {
                float4 val = isv ? *(const float4*)&vb[cur][row][seg * 4]
                                 : *(const float4*)&kb[cur][row][seg * 4];
                __stcs((float4*)(out_kv + ((((size_t)(isv ? 1 : 0) * B_ + b) * NH + h) * T_ + ckey) * HD + seg * 4), val);
            }
        }
    }

    // ---- write partials: stream id spp = sp*2 + kh ----
    const int spp = sp * 2 + kh;
    if (kj == 0) {
        size_t base = ((size_t)bh * NSPT + spp) * S_;
        g_pm[base + row0] = m0; g_pm[base + row1] = m1;
        g_pl[base + row0] = l0; g_pl[base + row1] = l1;
    }
    float* pa = g_pacc + (((size_t)bh * NSPT + spp) * S_ + qh * 8) * HD;
#pragma unroll
    for (int q = 0; q < 8; ++q) {
        float4 v = make_float4(acc[q][0], acc[q][1], acc[q][2], acc[q][3]);
        *(float4*)&pa[(size_t)q * HD + lane * 4] = v;
    }
}

// ---------------- combine split partials -> g_attn ----------------
__global__ __launch_bounds__(256) void k_comb() {
    const int bh = blockIdx.x;
    const int t = threadIdx.x;
    const int s = t >> 4, lj = t & 15;
    const int b = bh >> 4, h = bh & 15;

    float mv[NSPT], lv[NSPT];
#pragma unroll
    for (int sp = 0; sp < NSPT; ++sp) {
        size_t pidx = ((size_t)bh * NSPT + sp) * S_ + s;
        mv[sp] = g_pm[pidx];
        lv[sp] = g_pl[pidx];
    }
    float M = mv[0];
#pragma unroll
    for (int sp = 1; sp < NSPT; ++sp) M = fmaxf(M, mv[sp]);
    float w[NSPT], L = 0.f;
#pragma unroll
    for (int sp = 0; sp < NSPT; ++sp) { w[sp] = __expf(mv[sp] - M); L += lv[sp] * w[sp]; }
    float linv = 1.f / L;

    float o[8];
#pragma unroll
    for (int i = 0; i < 8; i++) o[i] = 0.f;
#pragma unroll
    for (int sp = 0; sp < NSPT; ++sp) {
        const float* pa = g_pacc + (((size_t)bh * NSPT + sp) * S_ + s) * HD;
        float4 a0 = *(const float4*)&pa[lj * 4];
        float4 a1 = *(const float4*)&pa[64 + lj * 4];
        o[0] += w[sp] * a0.x; o[1] += w[sp] * a0.y; o[2] += w[sp] * a0.z; o[3] += w[sp] * a0.w;
        o[4] += w[sp] * a1.x; o[5] += w[sp] * a1.y; o[6] += w[sp] * a1.z; o[7] += w[sp] * a1.w;
    }
    float* dst = g_attn + (size_t)(b * S_ + s) * DMODEL + h * HD;
#pragma unroll
    for (int i = 0; i < 4; i++) dst[lj * 4 + i]      = o[i]     * linv;
#pragma unroll
    for (int i = 0; i < 4; i++) dst[64 + lj * 4 + i] = o[4 + i] * linv;
}

// ---------------- launch ----------------
extern "C" void kernel_launch(void* const* d_in, const int* in_sizes, int n_in,
                              void* d_out, int out_size) {
    const float* x    = (const float*)d_in[0];
    const float* pk   = (const float*)d_in[1];
    const float* pv   = (const float*)d_in[2];
    const int*   mask = (const int*)  d_in[3];
    const float* Wp   = (const float*)d_in[4];
    const float* bp   = (const float*)d_in[5];
    const float* Wf   = (const float*)d_in[6];
    const float* bf   = (const float*)d_in[7];
    float* out    = (float*)d_out;
    float* out_ff = out;                               // ff_o: 128*2048 floats
    float* out_kv = out + (size_t)M_ * DMODEL;         // next_prefix_kv: [2][8][16][4112][128]

    k_init   <<<3072, 256>>>(bp, bf, out_ff);
    k_gemm   <<<dim3(48, 3), 256>>>(x, Wp, nullptr, 3 * DMODEL, 0);   // QKV, 144 blocks
    k_scatter<<<3072, 256>>>(out_kv);
    k_attn   <<<dim3(NH, B_, NSPLIT_G), 128>>>(pk, pv, mask, out_kv); // 640 blocks, 1 wave
    k_comb   <<<M_, 256>>>();
    k_gemm   <<<dim3(16, 8), 256>>>(nullptr, Wf, out_ff, DMODEL, 1);  // FF, 128 blocks
}